// round 1
// baseline (speedup 1.0000x reference)
#include <cuda_runtime.h>

#define B_  8
#define C_  512
#define T_  2048
#define CQ_ 64

// Scratch (device globals — no allocations allowed)
__device__ float g_q[B_ * CQ_ * T_];            // [B, Cq, T]
__device__ float g_k[B_ * CQ_ * T_];            // [B, Cq, T]
__device__ float g_v[B_ * C_  * T_];            // [B, C, T]
__device__ float g_s[(size_t)B_ * T_ * T_];     // [B, T, T] scores/probs (134 MB)

// ---------------------------------------------------------------------------
// Projection GEMM: O[b, m, n] = sum_k W[m,k] * X[b,k,n] + bias[m]
// W: [M,K] row-major (k contiguous). X: [B,K,T] (n=t contiguous).
// Tile 64x64, Kc=16, 256 threads, 4x4 microtile.
// ---------------------------------------------------------------------------
__global__ void proj_kernel(const float* __restrict__ W,
                            const float* __restrict__ bias,
                            const float* __restrict__ X,
                            float* __restrict__ O,
                            int M, int K)
{
    __shared__ float As[16][65];   // As[k][m] (transposed store, padded)
    __shared__ float Bs[16][64];   // Bs[k][n]

    const int b  = blockIdx.z;
    const int m0 = blockIdx.y * 64;
    const int n0 = blockIdx.x * 64;
    const float* Xb = X + (size_t)b * K * T_;
    float*       Ob = O + (size_t)b * M * T_;

    const int tid = threadIdx.x;
    const int tx = tid & 15;        // n micro
    const int ty = tid >> 4;        // m micro
    const int la_m = tid >> 2;      // 0..63
    const int la_k = (tid & 3) * 4; // 0,4,8,12
    const int lb_k = tid >> 4;      // 0..15
    const int lb_n = (tid & 15) * 4;

    float acc[4][4] = {};

    for (int k0 = 0; k0 < K; k0 += 16) {
        float4 a = *reinterpret_cast<const float4*>(&W[(size_t)(m0 + la_m) * K + k0 + la_k]);
        As[la_k + 0][la_m] = a.x;
        As[la_k + 1][la_m] = a.y;
        As[la_k + 2][la_m] = a.z;
        As[la_k + 3][la_m] = a.w;
        *reinterpret_cast<float4*>(&Bs[lb_k][lb_n]) =
            *reinterpret_cast<const float4*>(&Xb[(size_t)(k0 + lb_k) * T_ + n0 + lb_n]);
        __syncthreads();

        #pragma unroll
        for (int kk = 0; kk < 16; kk++) {
            float a0 = As[kk][ty * 4 + 0];
            float a1 = As[kk][ty * 4 + 1];
            float a2 = As[kk][ty * 4 + 2];
            float a3 = As[kk][ty * 4 + 3];
            float b0 = Bs[kk][tx * 4 + 0];
            float b1 = Bs[kk][tx * 4 + 1];
            float b2 = Bs[kk][tx * 4 + 2];
            float b3 = Bs[kk][tx * 4 + 3];
            acc[0][0] += a0 * b0; acc[0][1] += a0 * b1; acc[0][2] += a0 * b2; acc[0][3] += a0 * b3;
            acc[1][0] += a1 * b0; acc[1][1] += a1 * b1; acc[1][2] += a1 * b2; acc[1][3] += a1 * b3;
            acc[2][0] += a2 * b0; acc[2][1] += a2 * b1; acc[2][2] += a2 * b2; acc[2][3] += a2 * b3;
            acc[3][0] += a3 * b0; acc[3][1] += a3 * b1; acc[3][2] += a3 * b2; acc[3][3] += a3 * b3;
        }
        __syncthreads();
    }

    #pragma unroll
    for (int i = 0; i < 4; i++) {
        int m = m0 + ty * 4 + i;
        float bv = bias[m];
        float4 r = make_float4(acc[i][0] + bv, acc[i][1] + bv, acc[i][2] + bv, acc[i][3] + bv);
        *reinterpret_cast<float4*>(&Ob[(size_t)m * T_ + n0 + tx * 4]) = r;
    }
}

// ---------------------------------------------------------------------------
// Score GEMM: S[b,t,s] = sum_o Q[b,o,t] * K[b,o,s]
// Both operands [Cq, T] with t/s contiguous (TN-style; direct shared stores).
// ---------------------------------------------------------------------------
__global__ void score_kernel(const float* __restrict__ Q,
                             const float* __restrict__ Km,
                             float* __restrict__ S)
{
    __shared__ float As[16][64];   // As[k][m=t]
    __shared__ float Bs[16][64];   // Bs[k][n=s]

    const int b  = blockIdx.z;
    const int m0 = blockIdx.y * 64;
    const int n0 = blockIdx.x * 64;
    const float* Qb = Q  + (size_t)b * CQ_ * T_;
    const float* Kb = Km + (size_t)b * CQ_ * T_;

    const int tid = threadIdx.x;
    const int tx = tid & 15;
    const int ty = tid >> 4;
    const int lk = tid >> 4;        // 0..15
    const int ln = (tid & 15) * 4;

    float acc[4][4] = {};

    for (int k0 = 0; k0 < CQ_; k0 += 16) {
        *reinterpret_cast<float4*>(&As[lk][ln]) =
            *reinterpret_cast<const float4*>(&Qb[(size_t)(k0 + lk) * T_ + m0 + ln]);
        *reinterpret_cast<float4*>(&Bs[lk][ln]) =
            *reinterpret_cast<const float4*>(&Kb[(size_t)(k0 + lk) * T_ + n0 + ln]);
        __syncthreads();

        #pragma unroll
        for (int kk = 0; kk < 16; kk++) {
            float a0 = As[kk][ty * 4 + 0];
            float a1 = As[kk][ty * 4 + 1];
            float a2 = As[kk][ty * 4 + 2];
            float a3 = As[kk][ty * 4 + 3];
            float b0 = Bs[kk][tx * 4 + 0];
            float b1 = Bs[kk][tx * 4 + 1];
            float b2 = Bs[kk][tx * 4 + 2];
            float b3 = Bs[kk][tx * 4 + 3];
            acc[0][0] += a0 * b0; acc[0][1] += a0 * b1; acc[0][2] += a0 * b2; acc[0][3] += a0 * b3;
            acc[1][0] += a1 * b0; acc[1][1] += a1 * b1; acc[1][2] += a1 * b2; acc[1][3] += a1 * b3;
            acc[2][0] += a2 * b0; acc[2][1] += a2 * b1; acc[2][2] += a2 * b2; acc[2][3] += a2 * b3;
            acc[3][0] += a3 * b0; acc[3][1] += a3 * b1; acc[3][2] += a3 * b2; acc[3][3] += a3 * b3;
        }
        __syncthreads();
    }

    float* Sb = S + (size_t)b * T_ * T_;
    #pragma unroll
    for (int i = 0; i < 4; i++) {
        int m = m0 + ty * 4 + i;
        float4 r = make_float4(acc[i][0], acc[i][1], acc[i][2], acc[i][3]);
        *reinterpret_cast<float4*>(&Sb[(size_t)m * T_ + n0 + tx * 4]) = r;
    }
}

// ---------------------------------------------------------------------------
// Row softmax over last dim (T=2048). One block per row, 256 threads.
// ---------------------------------------------------------------------------
__global__ void softmax_kernel(float* __restrict__ S)
{
    const size_t row = blockIdx.x;
    float* p = S + row * T_;
    const int tid = threadIdx.x;
    const int lane = tid & 31;
    const int warp = tid >> 5;

    __shared__ float red[8];
    __shared__ float bcast;

    float v[8];
    float mx = -1e30f;
    #pragma unroll
    for (int i = 0; i < 8; i++) {
        v[i] = p[tid + i * 256];
        mx = fmaxf(mx, v[i]);
    }
    #pragma unroll
    for (int o = 16; o > 0; o >>= 1) mx = fmaxf(mx, __shfl_xor_sync(0xffffffffu, mx, o));
    if (lane == 0) red[warp] = mx;
    __syncthreads();
    if (tid == 0) {
        float m = red[0];
        #pragma unroll
        for (int w = 1; w < 8; w++) m = fmaxf(m, red[w]);
        bcast = m;
    }
    __syncthreads();
    mx = bcast;

    float sum = 0.0f;
    #pragma unroll
    for (int i = 0; i < 8; i++) {
        v[i] = __expf(v[i] - mx);
        sum += v[i];
    }
    #pragma unroll
    for (int o = 16; o > 0; o >>= 1) sum += __shfl_xor_sync(0xffffffffu, sum, o);
    __syncthreads();
    if (lane == 0) red[warp] = sum;
    __syncthreads();
    if (tid == 0) {
        float s = 0.0f;
        #pragma unroll
        for (int w = 0; w < 8; w++) s += red[w];
        bcast = 1.0f / s;
    }
    __syncthreads();
    float inv = bcast;

    #pragma unroll
    for (int i = 0; i < 8; i++) p[tid + i * 256] = v[i] * inv;
}

// ---------------------------------------------------------------------------
// Output GEMM + epilogue: O[b,c,t] = gamma * sum_s V[b,c,s]*P[b,t,s] + x[b,c,t]
// A = V[b] : [C, T]  (s contiguous)   -> transposed shared store
// B = P[b] : [T, T]  (s contiguous)   -> transposed shared store
// ---------------------------------------------------------------------------
__global__ void out_kernel(const float* __restrict__ V,
                           const float* __restrict__ P,
                           const float* __restrict__ x,
                           const float* __restrict__ gamma,
                           float* __restrict__ O)
{
    __shared__ float As[16][65];   // As[k][m=c]
    __shared__ float Bs[16][65];   // Bs[k][n=t]

    const int b  = blockIdx.z;
    const int m0 = blockIdx.y * 64;  // c tile
    const int n0 = blockIdx.x * 64;  // t tile
    const float* Vb = V + (size_t)b * C_ * T_;
    const float* Pb = P + (size_t)b * T_ * T_;

    const int tid = threadIdx.x;
    const int tx = tid & 15;
    const int ty = tid >> 4;
    const int l_r = tid >> 2;       // 0..63 (row within tile)
    const int l_k = (tid & 3) * 4;  // 0,4,8,12

    float acc[4][4] = {};

    for (int k0 = 0; k0 < T_; k0 += 16) {
        float4 a = *reinterpret_cast<const float4*>(&Vb[(size_t)(m0 + l_r) * T_ + k0 + l_k]);
        As[l_k + 0][l_r] = a.x;
        As[l_k + 1][l_r] = a.y;
        As[l_k + 2][l_r] = a.z;
        As[l_k + 3][l_r] = a.w;
        float4 bb = *reinterpret_cast<const float4*>(&Pb[(size_t)(n0 + l_r) * T_ + k0 + l_k]);
        Bs[l_k + 0][l_r] = bb.x;
        Bs[l_k + 1][l_r] = bb.y;
        Bs[l_k + 2][l_r] = bb.z;
        Bs[l_k + 3][l_r] = bb.w;
        __syncthreads();

        #pragma unroll
        for (int kk = 0; kk < 16; kk++) {
            float a0 = As[kk][ty * 4 + 0];
            float a1 = As[kk][ty * 4 + 1];
            float a2 = As[kk][ty * 4 + 2];
            float a3 = As[kk][ty * 4 + 3];
            float b0 = Bs[kk][tx * 4 + 0];
            float b1 = Bs[kk][tx * 4 + 1];
            float b2 = Bs[kk][tx * 4 + 2];
            float b3 = Bs[kk][tx * 4 + 3];
            acc[0][0] += a0 * b0; acc[0][1] += a0 * b1; acc[0][2] += a0 * b2; acc[0][3] += a0 * b3;
            acc[1][0] += a1 * b0; acc[1][1] += a1 * b1; acc[1][2] += a1 * b2; acc[1][3] += a1 * b3;
            acc[2][0] += a2 * b0; acc[2][1] += a2 * b1; acc[2][2] += a2 * b2; acc[2][3] += a2 * b3;
            acc[3][0] += a3 * b0; acc[3][1] += a3 * b1; acc[3][2] += a3 * b2; acc[3][3] += a3 * b3;
        }
        __syncthreads();
    }

    const float g = gamma[0];
    #pragma unroll
    for (int i = 0; i < 4; i++) {
        size_t idx = (size_t)b * C_ * T_ + (size_t)(m0 + ty * 4 + i) * T_ + n0 + tx * 4;
        float4 xi = *reinterpret_cast<const float4*>(&x[idx]);
        float4 r = make_float4(g * acc[i][0] + xi.x,
                               g * acc[i][1] + xi.y,
                               g * acc[i][2] + xi.z,
                               g * acc[i][3] + xi.w);
        *reinterpret_cast<float4*>(&O[idx]) = r;
    }
}

// ---------------------------------------------------------------------------
// Launch
// ---------------------------------------------------------------------------
extern "C" void kernel_launch(void* const* d_in, const int* in_sizes, int n_in,
                              void* d_out, int out_size)
{
    const float* x     = (const float*)d_in[0];
    const float* wq    = (const float*)d_in[1];
    const float* bq    = (const float*)d_in[2];
    const float* wk    = (const float*)d_in[3];
    const float* bk    = (const float*)d_in[4];
    const float* wv    = (const float*)d_in[5];
    const float* bv    = (const float*)d_in[6];
    const float* gamma = (const float*)d_in[7];
    float* out = (float*)d_out;

    float *q, *k, *v, *s;
    cudaGetSymbolAddress((void**)&q, g_q);
    cudaGetSymbolAddress((void**)&k, g_k);
    cudaGetSymbolAddress((void**)&v, g_v);
    cudaGetSymbolAddress((void**)&s, g_s);

    // Projections
    proj_kernel<<<dim3(T_ / 64, CQ_ / 64, B_), 256>>>(wq, bq, x, q, CQ_, C_);
    proj_kernel<<<dim3(T_ / 64, CQ_ / 64, B_), 256>>>(wk, bk, x, k, CQ_, C_);
    proj_kernel<<<dim3(T_ / 64, C_  / 64, B_), 256>>>(wv, bv, x, v, C_,  C_);

    // Scores
    score_kernel<<<dim3(T_ / 64, T_ / 64, B_), 256>>>(q, k, s);

    // Softmax
    softmax_kernel<<<B_ * T_, 256>>>(s);

    // Output + residual
    out_kernel<<<dim3(T_ / 64, C_ / 64, B_), 256>>>(v, s, x, gamma, out);
}

// round 2
// speedup vs baseline: 5.8069x; 5.8069x over previous
#include <cuda_runtime.h>
#include <cuda_bf16.h>
#include <cstdint>

using bf16 = __nv_bfloat16;

#define B_  8
#define C_  512
#define T_  2048
#define CQ_ 64

// ---------------------------------------------------------------------------
// Device-global scratch (no allocations allowed)
// ---------------------------------------------------------------------------
__device__ bf16  g_xb [B_ * C_ * T_];           // x in bf16
__device__ bf16  g_wqb[CQ_ * C_];
__device__ bf16  g_wkb[CQ_ * C_];
__device__ bf16  g_wvb[C_ * C_];
__device__ bf16  g_qb [B_ * CQ_ * T_];          // [B, Cq, T]
__device__ bf16  g_kb [B_ * CQ_ * T_];          // [B, Cq, T]
__device__ bf16  g_vb [B_ * C_  * T_];          // [B, C, T]
__device__ float g_s  [(size_t)B_ * T_ * T_];   // scores fp32
__device__ bf16  g_p  [(size_t)B_ * T_ * T_];   // probs bf16

// ---------------------------------------------------------------------------
// PTX helpers
// ---------------------------------------------------------------------------
__device__ __forceinline__ uint32_t cvta_s(const void* p) {
    return (uint32_t)__cvta_generic_to_shared(p);
}
__device__ __forceinline__ void ldsm_x4(uint32_t* r, uint32_t a) {
    asm volatile("ldmatrix.sync.aligned.m8n8.x4.shared.b16 {%0,%1,%2,%3},[%4];"
                 : "=r"(r[0]), "=r"(r[1]), "=r"(r[2]), "=r"(r[3]) : "r"(a));
}
__device__ __forceinline__ void ldsm_x4t(uint32_t* r, uint32_t a) {
    asm volatile("ldmatrix.sync.aligned.m8n8.x4.trans.shared.b16 {%0,%1,%2,%3},[%4];"
                 : "=r"(r[0]), "=r"(r[1]), "=r"(r[2]), "=r"(r[3]) : "r"(a));
}
__device__ __forceinline__ void ldsm_x2(uint32_t* r, uint32_t a) {
    asm volatile("ldmatrix.sync.aligned.m8n8.x2.shared.b16 {%0,%1},[%2];"
                 : "=r"(r[0]), "=r"(r[1]) : "r"(a));
}
__device__ __forceinline__ void ldsm_x2t(uint32_t* r, uint32_t a) {
    asm volatile("ldmatrix.sync.aligned.m8n8.x2.trans.shared.b16 {%0,%1},[%2];"
                 : "=r"(r[0]), "=r"(r[1]) : "r"(a));
}
__device__ __forceinline__ void mma_bf16(float* c, const uint32_t* a, const uint32_t* b) {
    asm volatile("mma.sync.aligned.m16n8k16.row.col.f32.bf16.bf16.f32 "
                 "{%0,%1,%2,%3},{%4,%5,%6,%7},{%8,%9},{%0,%1,%2,%3};"
                 : "+f"(c[0]), "+f"(c[1]), "+f"(c[2]), "+f"(c[3])
                 : "r"(a[0]), "r"(a[1]), "r"(a[2]), "r"(a[3]), "r"(b[0]), "r"(b[1]));
}

// ---------------------------------------------------------------------------
// fp32 -> bf16 convert (n divisible by 4)
// ---------------------------------------------------------------------------
__global__ void f2b_kernel(const float* __restrict__ in, bf16* __restrict__ out, int n4) {
    int i = blockIdx.x * blockDim.x + threadIdx.x;
    if (i >= n4) return;
    float4 v = *reinterpret_cast<const float4*>(in + (size_t)i * 4);
    __nv_bfloat162 lo = __floats2bfloat162_rn(v.x, v.y);
    __nv_bfloat162 hi = __floats2bfloat162_rn(v.z, v.w);
    uint2 pk;
    pk.x = *reinterpret_cast<uint32_t*>(&lo);
    pk.y = *reinterpret_cast<uint32_t*>(&hi);
    *reinterpret_cast<uint2*>(out + (size_t)i * 4) = pk;
}

// ---------------------------------------------------------------------------
// Projection: O[b,m,t] (bf16) = sum_k W[m,k]*X[b,k,t] + bias[m]
// A = W (non-trans, [m][k] k-contig), B = X (trans ldmatrix, [k][n] n-contig)
// Block tile 64m x 128n, K-chunk 64. 8 warps (2m x 4n), warp tile 32x32.
// ---------------------------------------------------------------------------
__global__ void proj_mma(const bf16* __restrict__ W, const float* __restrict__ bias,
                         const bf16* __restrict__ X, bf16* __restrict__ O,
                         int M, int K)
{
    __shared__ bf16 sA[64][72];    // [m][k]
    __shared__ bf16 sB[64][136];   // [k][n]

    const int b  = blockIdx.z;
    const int n0 = blockIdx.x * 128;
    const int m0 = blockIdx.y * 64;
    const bf16* Xb = X + (size_t)b * K * T_;
    bf16*       Ob = O + (size_t)b * M * T_;

    const int tid  = threadIdx.x;
    const int lane = tid & 31;
    const int w    = tid >> 5;
    const int wm   = (w >> 2) * 32;
    const int wn   = (w & 3) * 32;

    float acc[2][4][4] = {};

    for (int kc = 0; kc < K; kc += 64) {
        // load A: 64 rows x 64 bf16 (128B/row): 8 uint4 per row
        {
            int r = tid >> 3, c = (tid & 7) * 8;
            #pragma unroll
            for (int p = 0; p < 2; p++) {
                *reinterpret_cast<uint4*>(&sA[r + p * 32][c]) =
                    *reinterpret_cast<const uint4*>(&W[(size_t)(m0 + r + p * 32) * K + kc + c]);
            }
        }
        // load B: 64 rows(k) x 128 bf16 (256B/row): 16 uint4 per row
        {
            int r = tid >> 4, c = (tid & 15) * 8;
            #pragma unroll
            for (int p = 0; p < 4; p++) {
                *reinterpret_cast<uint4*>(&sB[r + p * 16][c]) =
                    *reinterpret_cast<const uint4*>(&Xb[(size_t)(kc + r + p * 16) * T_ + n0 + c]);
            }
        }
        __syncthreads();

        #pragma unroll
        for (int kk = 0; kk < 64; kk += 16) {
            uint32_t af[2][4], bf_[4][2];
            #pragma unroll
            for (int mi = 0; mi < 2; mi++) {
                uint32_t a = cvta_s(&sA[wm + mi * 16 + (lane & 15)][kk + (lane >> 4) * 8]);
                ldsm_x4(af[mi], a);
            }
            #pragma unroll
            for (int ni = 0; ni < 4; ni++) {
                int r = kk + ((lane >> 3) & 1) * 8 + (lane & 7);
                uint32_t a = cvta_s(&sB[r][wn + ni * 8]);
                ldsm_x2t(bf_[ni], a);
            }
            #pragma unroll
            for (int mi = 0; mi < 2; mi++)
                #pragma unroll
                for (int ni = 0; ni < 4; ni++)
                    mma_bf16(acc[mi][ni], af[mi], bf_[ni]);
        }
        __syncthreads();
    }

    // epilogue: bias + convert to bf16
    #pragma unroll
    for (int mi = 0; mi < 2; mi++) {
        int grow = m0 + wm + mi * 16 + (lane >> 2);
        float bv0 = bias[grow];
        float bv1 = bias[grow + 8];
        #pragma unroll
        for (int ni = 0; ni < 4; ni++) {
            int gcol = n0 + wn + ni * 8 + (lane & 3) * 2;
            __nv_bfloat162 v0 = __floats2bfloat162_rn(acc[mi][ni][0] + bv0, acc[mi][ni][1] + bv0);
            __nv_bfloat162 v1 = __floats2bfloat162_rn(acc[mi][ni][2] + bv1, acc[mi][ni][3] + bv1);
            *reinterpret_cast<__nv_bfloat162*>(&Ob[(size_t)grow * T_ + gcol]) = v0;
            *reinterpret_cast<__nv_bfloat162*>(&Ob[(size_t)(grow + 8) * T_ + gcol]) = v1;
        }
    }
}

// ---------------------------------------------------------------------------
// Scores: S[b,t,s] = sum_o Q[b,o,t] * K[b,o,s]    (fp32 out)
// A = Q^T (trans ldmatrix from [o][t]), B = K (trans ldmatrix from [o][s])
// K-dim = Cq = 64: single chunk, no loop.
// ---------------------------------------------------------------------------
__global__ void score_mma(const bf16* __restrict__ Q, const bf16* __restrict__ Km,
                          float* __restrict__ S)
{
    __shared__ bf16 sA[64][72];    // [k=o][m=t]
    __shared__ bf16 sB[64][136];   // [k=o][n=s]

    const int b  = blockIdx.z;
    const int n0 = blockIdx.x * 128;
    const int m0 = blockIdx.y * 64;
    const bf16* Qb = Q  + (size_t)b * CQ_ * T_;
    const bf16* Kb = Km + (size_t)b * CQ_ * T_;

    const int tid  = threadIdx.x;
    const int lane = tid & 31;
    const int w    = tid >> 5;
    const int wm   = (w >> 2) * 32;
    const int wn   = (w & 3) * 32;

    // load A: 64 rows(o) x 64 t
    {
        int r = tid >> 3, c = (tid & 7) * 8;
        #pragma unroll
        for (int p = 0; p < 2; p++)
            *reinterpret_cast<uint4*>(&sA[r + p * 32][c]) =
                *reinterpret_cast<const uint4*>(&Qb[(size_t)(r + p * 32) * T_ + m0 + c]);
    }
    // load B: 64 rows(o) x 128 s
    {
        int r = tid >> 4, c = (tid & 15) * 8;
        #pragma unroll
        for (int p = 0; p < 4; p++)
            *reinterpret_cast<uint4*>(&sB[r + p * 16][c]) =
                *reinterpret_cast<const uint4*>(&Kb[(size_t)(r + p * 16) * T_ + n0 + c]);
    }
    __syncthreads();

    float acc[2][4][4] = {};

    #pragma unroll
    for (int kk = 0; kk < 64; kk += 16) {
        uint32_t af[2][4], bf_[4][2];
        int g = lane >> 3;
        #pragma unroll
        for (int mi = 0; mi < 2; mi++) {
            uint32_t a = cvta_s(&sA[kk + (g >> 1) * 8 + (lane & 7)][wm + mi * 16 + (g & 1) * 8]);
            ldsm_x4t(af[mi], a);
        }
        #pragma unroll
        for (int ni = 0; ni < 4; ni++) {
            int r = kk + ((lane >> 3) & 1) * 8 + (lane & 7);
            uint32_t a = cvta_s(&sB[r][wn + ni * 8]);
            ldsm_x2t(bf_[ni], a);
        }
        #pragma unroll
        for (int mi = 0; mi < 2; mi++)
            #pragma unroll
            for (int ni = 0; ni < 4; ni++)
                mma_bf16(acc[mi][ni], af[mi], bf_[ni]);
    }

    float* Sb = S + (size_t)b * T_ * T_;
    #pragma unroll
    for (int mi = 0; mi < 2; mi++) {
        int grow = m0 + wm + mi * 16 + (lane >> 2);
        #pragma unroll
        for (int ni = 0; ni < 4; ni++) {
            int gcol = n0 + wn + ni * 8 + (lane & 3) * 2;
            *reinterpret_cast<float2*>(&Sb[(size_t)grow * T_ + gcol]) =
                make_float2(acc[mi][ni][0], acc[mi][ni][1]);
            *reinterpret_cast<float2*>(&Sb[(size_t)(grow + 8) * T_ + gcol]) =
                make_float2(acc[mi][ni][2], acc[mi][ni][3]);
        }
    }
}

// ---------------------------------------------------------------------------
// Row softmax: read fp32 S, write bf16 P. One block (256 thr) per row of 2048.
// ---------------------------------------------------------------------------
__global__ void softmax_kernel(const float* __restrict__ S, bf16* __restrict__ P)
{
    const size_t row = blockIdx.x;
    const float* sp = S + row * T_;
    bf16*        pp = P + row * T_;
    const int tid = threadIdx.x;
    const int lane = tid & 31;
    const int warp = tid >> 5;

    __shared__ float red[8];
    __shared__ float bcast;

    float v[8];
    float4 a = *reinterpret_cast<const float4*>(sp + tid * 8);
    float4 c = *reinterpret_cast<const float4*>(sp + tid * 8 + 4);
    v[0] = a.x; v[1] = a.y; v[2] = a.z; v[3] = a.w;
    v[4] = c.x; v[5] = c.y; v[6] = c.z; v[7] = c.w;

    float mx = v[0];
    #pragma unroll
    for (int i = 1; i < 8; i++) mx = fmaxf(mx, v[i]);
    #pragma unroll
    for (int o = 16; o > 0; o >>= 1) mx = fmaxf(mx, __shfl_xor_sync(0xffffffffu, mx, o));
    if (lane == 0) red[warp] = mx;
    __syncthreads();
    if (tid == 0) {
        float m = red[0];
        #pragma unroll
        for (int i = 1; i < 8; i++) m = fmaxf(m, red[i]);
        bcast = m;
    }
    __syncthreads();
    mx = bcast;

    float sum = 0.0f;
    #pragma unroll
    for (int i = 0; i < 8; i++) { v[i] = __expf(v[i] - mx); sum += v[i]; }
    #pragma unroll
    for (int o = 16; o > 0; o >>= 1) sum += __shfl_xor_sync(0xffffffffu, sum, o);
    __syncthreads();
    if (lane == 0) red[warp] = sum;
    __syncthreads();
    if (tid == 0) {
        float s = 0.0f;
        #pragma unroll
        for (int i = 0; i < 8; i++) s += red[i];
        bcast = 1.0f / s;
    }
    __syncthreads();
    float inv = bcast;

    uint4 pk;
    __nv_bfloat162 p0 = __floats2bfloat162_rn(v[0] * inv, v[1] * inv);
    __nv_bfloat162 p1 = __floats2bfloat162_rn(v[2] * inv, v[3] * inv);
    __nv_bfloat162 p2 = __floats2bfloat162_rn(v[4] * inv, v[5] * inv);
    __nv_bfloat162 p3 = __floats2bfloat162_rn(v[6] * inv, v[7] * inv);
    pk.x = *reinterpret_cast<uint32_t*>(&p0);
    pk.y = *reinterpret_cast<uint32_t*>(&p1);
    pk.z = *reinterpret_cast<uint32_t*>(&p2);
    pk.w = *reinterpret_cast<uint32_t*>(&p3);
    *reinterpret_cast<uint4*>(pp + tid * 8) = pk;
}

// ---------------------------------------------------------------------------
// Output: O[b,c,t] = gamma * sum_s V[b,c,s]*P[b,t,s] + x[b,c,t]   (fp32 out)
// A = V (non-trans, [c][s] k-contig), B = P (non-trans, [t][s] k-contig)
// Block tile 64m(c) x 128n(t), K-chunk 64, K total 2048.
// ---------------------------------------------------------------------------
__global__ void out_mma(const bf16* __restrict__ V, const bf16* __restrict__ P,
                        const float* __restrict__ x, const float* __restrict__ gamma,
                        float* __restrict__ O)
{
    __shared__ bf16 sA[64][72];    // [m=c][k=s]
    __shared__ bf16 sB[128][72];   // [n=t][k=s]

    const int b  = blockIdx.z;
    const int n0 = blockIdx.x * 128;
    const int m0 = blockIdx.y * 64;
    const bf16* Vb = V + (size_t)b * C_ * T_;
    const bf16* Pb = P + (size_t)b * T_ * T_;

    const int tid  = threadIdx.x;
    const int lane = tid & 31;
    const int w    = tid >> 5;
    const int wm   = (w >> 2) * 32;
    const int wn   = (w & 3) * 32;

    float acc[2][4][4] = {};

    for (int kc = 0; kc < T_; kc += 64) {
        // A: 64 rows(c) x 64 s
        {
            int r = tid >> 3, c = (tid & 7) * 8;
            #pragma unroll
            for (int p = 0; p < 2; p++)
                *reinterpret_cast<uint4*>(&sA[r + p * 32][c]) =
                    *reinterpret_cast<const uint4*>(&Vb[(size_t)(m0 + r + p * 32) * T_ + kc + c]);
        }
        // B: 128 rows(t) x 64 s
        {
            int r = tid >> 3, c = (tid & 7) * 8;
            #pragma unroll
            for (int p = 0; p < 4; p++)
                *reinterpret_cast<uint4*>(&sB[r + p * 32][c]) =
                    *reinterpret_cast<const uint4*>(&Pb[(size_t)(n0 + r + p * 32) * T_ + kc + c]);
        }
        __syncthreads();

        #pragma unroll
        for (int kk = 0; kk < 64; kk += 16) {
            uint32_t af[2][4], bf_[4][2];
            #pragma unroll
            for (int mi = 0; mi < 2; mi++) {
                uint32_t a = cvta_s(&sA[wm + mi * 16 + (lane & 15)][kk + (lane >> 4) * 8]);
                ldsm_x4(af[mi], a);
            }
            #pragma unroll
            for (int ni = 0; ni < 4; ni++) {
                int r = wn + ni * 8 + (lane & 7);
                uint32_t a = cvta_s(&sB[r][kk + ((lane >> 3) & 1) * 8]);
                ldsm_x2(bf_[ni], a);
            }
            #pragma unroll
            for (int mi = 0; mi < 2; mi++)
                #pragma unroll
                for (int ni = 0; ni < 4; ni++)
                    mma_bf16(acc[mi][ni], af[mi], bf_[ni]);
        }
        __syncthreads();
    }

    const float g = gamma[0];
    #pragma unroll
    for (int mi = 0; mi < 2; mi++) {
        int grow = m0 + wm + mi * 16 + (lane >> 2);
        #pragma unroll
        for (int ni = 0; ni < 4; ni++) {
            int gcol = n0 + wn + ni * 8 + (lane & 3) * 2;
            size_t i0 = (size_t)b * C_ * T_ + (size_t)grow * T_ + gcol;
            size_t i1 = (size_t)b * C_ * T_ + (size_t)(grow + 8) * T_ + gcol;
            float2 x0 = *reinterpret_cast<const float2*>(&x[i0]);
            float2 x1 = *reinterpret_cast<const float2*>(&x[i1]);
            *reinterpret_cast<float2*>(&O[i0]) =
                make_float2(g * acc[mi][ni][0] + x0.x, g * acc[mi][ni][1] + x0.y);
            *reinterpret_cast<float2*>(&O[i1]) =
                make_float2(g * acc[mi][ni][2] + x1.x, g * acc[mi][ni][3] + x1.y);
        }
    }
}

// ---------------------------------------------------------------------------
// Launch
// ---------------------------------------------------------------------------
extern "C" void kernel_launch(void* const* d_in, const int* in_sizes, int n_in,
                              void* d_out, int out_size)
{
    const float* x     = (const float*)d_in[0];
    const float* wq    = (const float*)d_in[1];
    const float* bq    = (const float*)d_in[2];
    const float* wk    = (const float*)d_in[3];
    const float* bk    = (const float*)d_in[4];
    const float* wv    = (const float*)d_in[5];
    const float* bv    = (const float*)d_in[6];
    const float* gamma = (const float*)d_in[7];
    float* out = (float*)d_out;

    bf16 *xb, *wqb, *wkb, *wvb, *qb, *kb, *vb, *pb;
    float* s;
    cudaGetSymbolAddress((void**)&xb,  g_xb);
    cudaGetSymbolAddress((void**)&wqb, g_wqb);
    cudaGetSymbolAddress((void**)&wkb, g_wkb);
    cudaGetSymbolAddress((void**)&wvb, g_wvb);
    cudaGetSymbolAddress((void**)&qb,  g_qb);
    cudaGetSymbolAddress((void**)&kb,  g_kb);
    cudaGetSymbolAddress((void**)&vb,  g_vb);
    cudaGetSymbolAddress((void**)&s,   g_s);
    cudaGetSymbolAddress((void**)&pb,  g_p);

    // converts
    {
        int n4 = (B_ * C_ * T_) / 4;
        f2b_kernel<<<(n4 + 255) / 256, 256>>>(x, xb, n4);
        n4 = (CQ_ * C_) / 4;
        f2b_kernel<<<(n4 + 255) / 256, 256>>>(wq, wqb, n4);
        f2b_kernel<<<(n4 + 255) / 256, 256>>>(wk, wkb, n4);
        n4 = (C_ * C_) / 4;
        f2b_kernel<<<(n4 + 255) / 256, 256>>>(wv, wvb, n4);
    }

    // projections (bf16 tensor core)
    proj_mma<<<dim3(T_ / 128, CQ_ / 64, B_), 256>>>(wqb, bq, xb, qb, CQ_, C_);
    proj_mma<<<dim3(T_ / 128, CQ_ / 64, B_), 256>>>(wkb, bk, xb, kb, CQ_, C_);
    proj_mma<<<dim3(T_ / 128, C_  / 64, B_), 256>>>(wvb, bv, xb, vb, C_,  C_);

    // scores
    score_mma<<<dim3(T_ / 128, T_ / 64, B_), 256>>>(qb, kb, s);

    // softmax (fp32 in, bf16 out)
    softmax_kernel<<<B_ * T_, 256>>>(s, pb);

    // output + residual
    out_mma<<<dim3(T_ / 128, C_ / 64, B_), 256>>>(vb, pb, x, gamma, out);
}